// round 9
// baseline (speedup 1.0000x reference)
#include <cuda_runtime.h>
#include <cstddef>
#include <cstdint>

#define BATCH   16
#define CIN     256
#define NPIX    1024
#define HEADS   8
#define DH      64
#define INNER   512
#define MQKV    1536
#define OUT_ELEMS   (BATCH * CIN * NPIX)            // 4194304

// Scratch (device globals: allocation-free rule)
__device__ float g_qkv [(size_t)BATCH * MQKV  * NPIX];   // [b][1536][1024] q|k|v (fp32)
__device__ float g_xT  [(size_t)BATCH * NPIX  * CIN ];   // [b][p][c]   tf32-rounded
__device__ float g_ctxT[(size_t)BATCH * NPIX  * INNER];  // [b][p][hd]  tf32-rounded
__device__ float g_w   [(size_t)MQKV * CIN ];            // [1536][256] tf32-rounded (Wq|Wkv)
__device__ float g_woR [(size_t)CIN  * INNER];           // [256][512]  tf32-rounded

__device__ __forceinline__ float f2tf32f(float f) {
    uint32_t u;
    asm("cvt.rna.tf32.f32 %0, %1;" : "=r"(u) : "f"(f));
    return __uint_as_float(u);
}

// ---------------------------------------------------------------------------
// Prep 1: transpose + tf32-round x: [b][c][p] -> g_xT[b][p][c]
// ---------------------------------------------------------------------------
__global__ void __launch_bounds__(256)
prep_x(const float* __restrict__ x)
{
    __shared__ float sm[32][33];
    const int b = blockIdx.z, ct = blockIdx.y, pt = blockIdx.x;
    const int t = threadIdx.x;
    const float* xb = x + ((size_t)b * CIN + ct * 32) * NPIX + pt * 32;
    const int cl = t >> 5, pl = t & 31;
    #pragma unroll
    for (int i = 0; i < 4; i++)
        sm[cl + i * 8][pl] = xb[(size_t)(cl + i * 8) * NPIX + pl];
    __syncthreads();
    float* xo = g_xT + ((size_t)b * NPIX + pt * 32) * CIN + ct * 32;
    const int pr = t >> 5, cc = t & 31;
    #pragma unroll
    for (int i = 0; i < 4; i++)
        xo[(size_t)(pr + i * 8) * CIN + cc] = f2tf32f(sm[cc][pr + i * 8]);
}

// ---------------------------------------------------------------------------
// Prep 2: round weights into g_w (Wq|Wkv) and g_woR. float4 grid-stride.
// ---------------------------------------------------------------------------
__global__ void __launch_bounds__(256)
prep_w(const float* __restrict__ Wq, const float* __restrict__ Wkv,
       const float* __restrict__ Wo)
{
    const int i = blockIdx.x * 256 + threadIdx.x;   // float4 index, grid covers 131072
    float4 v; float* dst;
    if (i < 32768)            { v = ((const float4*)Wq)[i];           dst = g_w   + (size_t)i * 4; }
    else if (i < 98304)       { v = ((const float4*)Wkv)[i - 32768];  dst = g_w   + (size_t)i * 4; }
    else                      { v = ((const float4*)Wo)[i - 98304];   dst = g_woR + (size_t)(i - 98304) * 4; }
    float4 r;
    r.x = f2tf32f(v.x); r.y = f2tf32f(v.y); r.z = f2tf32f(v.z); r.w = f2tf32f(v.w);
    *(float4*)dst = r;
}

// ---------------------------------------------------------------------------
// Pipelined TF32 tensor-core GEMM, templated on BN tile (128 for QKV, 64 for
// out-projection to fill the chip). C[z][m][p] = sum_k A[m][k]*B[z][p][k]+bias
// ---------------------------------------------------------------------------
#define BM 128
#define BK 32
#define RSW 36
#define ATILE_B (128 * RSW * 4)      // 18432 bytes

__device__ __forceinline__ void cp16(uint32_t dst, const void* src) {
    asm volatile("cp.async.cg.shared.global [%0], [%1], 16;" :: "r"(dst), "l"(src));
}
__device__ __forceinline__ void cp4z(uint32_t dst, const void* src, bool ok) {
    int sz = ok ? 4 : 0;
    asm volatile("cp.async.ca.shared.global [%0], [%1], 4, %2;"
                 :: "r"(dst), "l"(src), "r"(sz));
}
__device__ __forceinline__ void cp_commit() {
    asm volatile("cp.async.commit_group;" ::: "memory");
}
__device__ __forceinline__ void cp_wait1() {
    asm volatile("cp.async.wait_group 1;" ::: "memory");
}
__device__ __forceinline__ void cp_wait0() {
    asm volatile("cp.async.wait_group 0;" ::: "memory");
}
__device__ __forceinline__ void ldm_x4(uint32_t r[4], uint32_t saddr) {
    asm volatile("ldmatrix.sync.aligned.m8n8.x4.shared.b16 {%0,%1,%2,%3}, [%4];"
        : "=r"(r[0]), "=r"(r[1]), "=r"(r[2]), "=r"(r[3]) : "r"(saddr));
}
__device__ __forceinline__ void mma_tf32(float c[4], const uint32_t a[4], const uint32_t b[2]) {
    asm volatile(
        "mma.sync.aligned.m16n8k8.row.col.f32.tf32.tf32.f32 "
        "{%0,%1,%2,%3},{%4,%5,%6,%7},{%8,%9},{%0,%1,%2,%3};"
        : "+f"(c[0]), "+f"(c[1]), "+f"(c[2]), "+f"(c[3])
        : "r"(a[0]), "r"(a[1]), "r"(a[2]), "r"(a[3]), "r"(b[0]), "r"(b[1]));
}

extern __shared__ uint8_t g_dsmem[];

template<int BNt>
__global__ void __launch_bounds__(256, 2)
gemm_pipe(int a_sel, int b_sel, float* __restrict__ Cext, int c_sel,
          const float* __restrict__ bias, int M, int K)
{
    constexpr int WN   = BNt / 2;            // warp n-extent (2 warps in n)
    constexpr int NJ   = WN / 8;             // 8x8 n-frags per warp
    constexpr int BIT  = BNt / 32;           // B staging iterations
    constexpr int BTILE_B = BNt * RSW * 4;
    constexpr int STAGE_Bc = ATILE_B + BTILE_B;

    const int n0 = blockIdx.x * BNt;
    const int m0 = blockIdx.y * BM;
    const int z  = blockIdx.z;

    const float* __restrict__ A  = (a_sel == 1) ? g_w : g_woR;
    const float* __restrict__ Bm = (b_sel == 1) ? g_xT : g_ctxT;
    float* __restrict__ C        = (c_sel == 1) ? g_qkv : Cext;

    const float* __restrict__ Ab = A + (size_t)m0 * K;
    const float* __restrict__ Bb = Bm + ((size_t)z * NPIX + n0) * K;
    C += (size_t)z * M * NPIX + (size_t)m0 * NPIX + n0;

    const uint32_t sbase = (uint32_t)__cvta_generic_to_shared(g_dsmem);

    const int tid  = threadIdx.x;
    const int lane = tid & 31;
    const int warp = tid >> 5;
    const int wm0  = (warp >> 1) * 32;
    const int wn0  = (warp & 1) * WN;
    const int grp  = lane >> 2;
    const int qid  = lane & 3;

    const int sr  = tid >> 3;
    const int seg = tid & 7;

    const int a_mrow = ((lane >> 3) & 1) * 8 + (lane & 7);
    const int a_koff = ((lane >> 4) & 1) * 4;
    const int b_nrow = ((lane >> 4) & 1) * 8 + (lane & 7);
    const int b_koff = ((lane >> 3) & 1) * 4;

    float acc[2][NJ][4];
    #pragma unroll
    for (int mt = 0; mt < 2; mt++)
        #pragma unroll
        for (int j = 0; j < NJ; j++)
            #pragma unroll
            for (int e = 0; e < 4; e++) acc[mt][j][e] = 0.f;

    const int NT = K / BK;

    auto stage = [&](int kt, int s) {
        const uint32_t aB = sbase + s * STAGE_Bc;
        const uint32_t bB = aB + ATILE_B;
        const int kw = kt * BK + seg * 4;
        #pragma unroll
        for (int it = 0; it < 4; it++) {
            int r = sr + it * 32;
            cp16(aB + r * (RSW * 4) + seg * 16, Ab + (size_t)r * K + kw);
        }
        #pragma unroll
        for (int it = 0; it < BIT; it++) {
            int r = sr + it * 32;
            cp16(bB + r * (RSW * 4) + seg * 16, Bb + (size_t)r * K + kw);
        }
    };

    stage(0, 0);
    cp_commit();

    for (int kt = 0; kt < NT; kt++) {
        if (kt + 1 < NT) stage(kt + 1, (kt + 1) & 1);
        cp_commit();
        cp_wait1();
        __syncthreads();

        const uint32_t aS = sbase + (kt & 1) * STAGE_Bc;
        const uint32_t bS = aS + ATILE_B;

        #pragma unroll
        for (int ks = 0; ks < 4; ks++) {
            uint32_t afr[2][4];
            #pragma unroll
            for (int mt = 0; mt < 2; mt++)
                ldm_x4(afr[mt], aS + (wm0 + mt * 16 + a_mrow) * (RSW * 4)
                                   + (ks * 8 + a_koff) * 4);
            uint32_t bfr[NJ][2];
            #pragma unroll
            for (int jj = 0; jj < NJ / 2; jj++) {
                uint32_t r[4];
                ldm_x4(r, bS + (wn0 + jj * 16 + b_nrow) * (RSW * 4)
                             + (ks * 8 + b_koff) * 4);
                bfr[jj * 2 + 0][0] = r[0]; bfr[jj * 2 + 0][1] = r[1];
                bfr[jj * 2 + 1][0] = r[2]; bfr[jj * 2 + 1][1] = r[3];
            }
            #pragma unroll
            for (int mt = 0; mt < 2; mt++)
                #pragma unroll
                for (int j = 0; j < NJ; j++)
                    mma_tf32(acc[mt][j], afr[mt], bfr[j]);
        }
        __syncthreads();
    }

    #pragma unroll
    for (int mt = 0; mt < 2; mt++) {
        #pragma unroll
        for (int e2 = 0; e2 < 2; e2++) {
            int mloc = wm0 + mt * 16 + grp + e2 * 8;
            float bv = bias ? bias[m0 + mloc] : 0.f;
            #pragma unroll
            for (int j = 0; j < NJ; j++) {
                float2 r;
                r.x = acc[mt][j][e2 * 2 + 0] + bv;
                r.y = acc[mt][j][e2 * 2 + 1] + bv;
                *(float2*)(C + (size_t)mloc * NPIX + wn0 + j * 8 + 2 * qid) = r;
            }
        }
    }
}

// ---------------------------------------------------------------------------
// 3x3 windowed attention, seamless k->v cp.async pipeline.
// Block = 8row x 32col slab of one (b,h); warp w stages d-plane (dc+w) of the
// 10x34 zero-padded halo via cp.async zfill (OOB -> 0 == zero-padded unfold).
// Separate k (bufs 0,1) and v (bufs 2,3) double buffers; one uniform group
// sequence k0..k7,v0..v7 so softmax/attn-store overlap v staging.
// Emits attn [b,h,n,9] and ctx transposed + tf32-rounded g_ctxT[b][p][h*64+d].
// ---------------------------------------------------------------------------
#define DCH 8
#define TROWS 10
#define TCOLS 34
#define PLANE_W (TROWS * TCOLS)          // 340 words per d-plane
#define TILE_BYTES (DCH * PLANE_W * 4)   // 10880 bytes per buffer

__global__ void __launch_bounds__(256)
attn_kernel(float* __restrict__ attn_out)
{
    __shared__ float tile[4][DCH][TROWS][TCOLS];   // 43.5 KB: k bufs 0,1; v bufs 2,3

    const int tid  = threadIdx.x;
    const int lane = tid & 31;
    const int warp = tid >> 5;
    const int ry   = warp;            // row within slab
    const int x    = lane;            // col
    const int r0   = blockIdx.x * 8;
    const int h    = blockIdx.y;
    const int b    = blockIdx.z;
    const int p    = (r0 + ry) * 32 + x;

    const float* __restrict__ qb = g_qkv + ((size_t)b * MQKV +        h * DH) * NPIX;
    const float* __restrict__ kb = g_qkv + ((size_t)b * MQKV +  512 + h * DH) * NPIX;
    const float* __restrict__ vb = g_qkv + ((size_t)b * MQKV + 1024 + h * DH) * NPIX;

    const uint32_t tb = (uint32_t)__cvta_generic_to_shared(&tile[0][0][0][0]);

    // warp stages plane (dc + warp) into buffer buf
    auto stage = [&](const float* __restrict__ src_base, int dc, int buf) {
        const float* __restrict__ src = src_base + (size_t)(dc + warp) * NPIX;
        const uint32_t dst = tb + (uint32_t)(buf * TILE_BYTES + warp * (PLANE_W * 4));
        #pragma unroll
        for (int rr = 0; rr < TROWS; rr++) {
            const int gy = r0 + rr - 1;
            const bool rowok = ((unsigned)gy < 32u);
            const int gx = lane - 1;
            cp4z(dst + (rr * TCOLS + lane) * 4, src + gy * 32 + gx,
                 rowok && ((unsigned)gx < 32u));
            if (lane < 2) {
                const int gx2 = lane + 31;
                cp4z(dst + (rr * TCOLS + lane + 32) * 4, src + gy * 32 + gx2,
                     rowok && ((unsigned)gx2 < 32u));
            }
        }
    };

    // ---------------- Pass 1: dots = q . k ----------------
    float dots[9];
    #pragma unroll
    for (int w = 0; w < 9; w++) dots[w] = 0.f;

    stage(kb, 0, 0); cp_commit();
    stage(kb, DCH, 1); cp_commit();

    #pragma unroll 1
    for (int c = 0; c < DH / DCH; c++) {
        cp_wait1();                          // committed = c+2, need group c
        __syncthreads();
        const int buf = c & 1;
        const int dc  = c * DCH;
        float qv[DCH];
        #pragma unroll
        for (int dd = 0; dd < DCH; dd++)
            qv[dd] = qb[(size_t)(dc + dd) * NPIX + p];
        #pragma unroll
        for (int dd = 0; dd < DCH; dd++)
            #pragma unroll
            for (int w = 0; w < 9; w++)
                dots[w] += qv[dd] * tile[buf][dd][ry + w / 3][x + w % 3];
        __syncthreads();
        if (c + 2 < DH / DCH) stage(kb, (c + 2) * DCH, (c + 2) & 1);
        else                  stage(vb, (c + 2 - DH / DCH) * DCH, 2 + ((c + 2) & 1));
        cp_commit();
    }

    // softmax over 9 (OOB logits exactly 0) — overlaps v0/v1 staging
    const float scale = 0.125f;
    float mx = -1e30f;
    #pragma unroll
    for (int w = 0; w < 9; w++) { dots[w] *= scale; mx = fmaxf(mx, dots[w]); }
    float a[9], sum = 0.f;
    #pragma unroll
    for (int w = 0; w < 9; w++) { a[w] = expf(dots[w] - mx); sum += a[w]; }
    float inv = 1.f / sum;
    #pragma unroll
    for (int w = 0; w < 9; w++) a[w] *= inv;

    {
        float* ao = attn_out + ((size_t)(b * HEADS + h) * NPIX + p) * 9;
        #pragma unroll
        for (int w = 0; w < 9; w++) ao[w] = a[w];
    }

    // ---------------- Pass 2: ctx = attn . v ----------------
    float* __restrict__ ct = g_ctxT + ((size_t)b * NPIX + p) * INNER + h * DH;

    #pragma unroll 1
    for (int c = 0; c < DH / DCH; c++) {
        if (c == DH / DCH - 1) cp_wait0(); else cp_wait1();
        __syncthreads();
        const int buf = 2 + (c & 1);
        const int dc  = c * DCH;
        float acc8[DCH];
        #pragma unroll
        for (int dd = 0; dd < DCH; dd++) {
            float sacc = 0.f;
            #pragma unroll
            for (int w = 0; w < 9; w++)
                sacc += a[w] * tile[buf][dd][ry + w / 3][x + w % 3];
            acc8[dd] = f2tf32f(sacc);
        }
        *(float4*)(ct + dc)     = make_float4(acc8[0], acc8[1], acc8[2], acc8[3]);
        *(float4*)(ct + dc + 4) = make_float4(acc8[4], acc8[5], acc8[6], acc8[7]);
        __syncthreads();
        if (c + 2 < DH / DCH) { stage(vb, (c + 2) * DCH, 2 + ((c + 2) & 1)); cp_commit(); }
    }
}

// ---------------------------------------------------------------------------
extern "C" void kernel_launch(void* const* d_in, const int* in_sizes, int n_in,
                              void* d_out, int out_size)
{
    const float* x   = (const float*)d_in[0];
    const float* Wq  = (const float*)d_in[1];
    const float* Wkv = (const float*)d_in[2];
    const float* Wo  = (const float*)d_in[3];
    const float* bo  = (const float*)d_in[4];
    float* out = (float*)d_out;     // out (4194304) | attn (1179648)

    constexpr int SMEM128 = 2 * (ATILE_B + 128 * RSW * 4);   // 73728
    constexpr int SMEM64  = 2 * (ATILE_B + 64 * RSW * 4);    // 55296

    static int smem_set = 0;
    if (!smem_set) {
        cudaFuncSetAttribute(gemm_pipe<128>,
                             cudaFuncAttributeMaxDynamicSharedMemorySize, SMEM128);
        cudaFuncSetAttribute(gemm_pipe<64>,
                             cudaFuncAttributeMaxDynamicSharedMemorySize, SMEM64);
        smem_set = 1;
    }

    // prep: transpose+round x, round weights
    {
        dim3 g(32, 8, BATCH);
        prep_x<<<g, 256>>>(x);
        prep_w<<<512, 256>>>(Wq, Wkv, Wo);
    }

    // QKV: g_qkv[b][m][p] = g_w[m][:] . g_xT[b][p][:]
    {
        dim3 grid(NPIX / 128, MQKV / BM, BATCH);   // (8, 12, 16)
        gemm_pipe<128><<<grid, 256, SMEM128>>>(1, 1, nullptr, 1, nullptr, MQKV, CIN);
    }

    // attention -> attn tail + g_ctxT
    {
        dim3 grid(4, HEADS, BATCH);
        attn_kernel<<<grid, 256>>>(out + OUT_ELEMS);
    }

    // out projection: out[b][c][p] = g_woR[c][:] . g_ctxT[b][p][:] + bo[c]
    {
        dim3 grid(NPIX / 64, CIN / BM, BATCH);     // (16, 2, 16) = 512 blocks
        gemm_pipe<64><<<grid, 256, SMEM64>>>(2, 2, out, 0, bo, CIN, INNER);
    }
}